// round 15
// baseline (speedup 1.0000x reference)
#include <cuda_runtime.h>
#include <cuda_fp16.h>
#include <cstdint>

#define OUT_F 11008
#define IN_F  4096
#define BATCH 32
#define GROUP 128

#define OB      128                  // M tile
#define OTILES  (OUT_F / OB)         // 86
#define KSPLIT  16
#define KRANGE  (IN_F / KSPLIT)      // 256
#define KC      128                  // chunk == GROUP (scale-rescale trick)
#define NCH     (KRANGE / KC)        // 2
#define THREADS 256
#define PWROW   (IN_F / 8)           // 512 words per output row

#define APITCH_B 80                  // A packed row pitch (64B data + 16 pad)
#define BPITCH_B 272                 // B row pitch (256B data + 16 pad)

// smem arena (bytes): A 2x10240, B 2x8704
#define SA0 0
#define SA1 10240
#define SB0 20480
#define SB1 29184
#define SMTOT 37888

#define DQ_MASK  0x000f000fu
#define DQ_MAGIC 0x64086408u         // fp16x2 (1032, 1032)

__device__ __half g_xh[BATCH * IN_F];    // x fp16, k-permuted

__device__ __forceinline__ uint32_t smem_u32(const void* p) {
    uint32_t a;
    asm("{ .reg .u64 t; cvta.to.shared.u64 t, %1; cvt.u32.u64 %0, t; }"
        : "=r"(a) : "l"(p));
    return a;
}
__device__ __forceinline__ void ldsm4(uint32_t& r0, uint32_t& r1, uint32_t& r2,
                                      uint32_t& r3, uint32_t addr) {
    asm volatile("ldmatrix.sync.aligned.m8n8.x4.shared.b16 {%0,%1,%2,%3}, [%4];"
                 : "=r"(r0), "=r"(r1), "=r"(r2), "=r"(r3) : "r"(addr));
}
__device__ __forceinline__ void lds64(uint32_t& lo, uint32_t& hi, uint32_t addr) {
    asm volatile("ld.shared.v2.u32 {%0,%1}, [%2];" : "=r"(lo), "=r"(hi) : "r"(addr));
}
__device__ __forceinline__ void mma_f16(float* c,
                                        uint32_t a0, uint32_t a1, uint32_t a2,
                                        uint32_t a3, uint32_t b0, uint32_t b1) {
    asm volatile(
        "mma.sync.aligned.m16n8k16.row.col.f32.f16.f16.f32 "
        "{%0,%1,%2,%3}, {%4,%5,%6,%7}, {%8,%9}, {%0,%1,%2,%3};"
        : "+f"(c[0]), "+f"(c[1]), "+f"(c[2]), "+f"(c[3])
        : "r"(a0), "r"(a1), "r"(a2), "r"(a3), "r"(b0), "r"(b1));
}
__device__ __forceinline__ void cp16(uint32_t saddr, const void* gaddr) {
    asm volatile("cp.async.cg.shared.global [%0], [%1], 16;"
                 :: "r"(saddr), "l"(gaddr) : "memory");
}
// nibbles (c, c+4) of p -> f16x2 of exact signed int4 values
__device__ __forceinline__ uint32_t dqf(uint32_t p, int sh) {
    uint32_t r = ((p >> sh) & DQ_MASK) ^ DQ_MAGIC;
    const uint32_t mg = DQ_MAGIC;
    __half2 h = __hsub2(*reinterpret_cast<__half2*>(&r),
                        *reinterpret_cast<const __half2*>(&mg));
    return *reinterpret_cast<uint32_t*>(&h);
}

// ---------------- prep: x fp16 (k-permuted) + out = bias (float4) ----------------
__global__ void prep_kernel(const float* __restrict__ x,
                            const float* __restrict__ bias,
                            float* __restrict__ out) {
    int i = blockIdx.x * blockDim.x + threadIdx.x;
    if (i < BATCH * IN_F) {
        int b = i >> 12;
        int k = i & (IN_F - 1);
        int j = k & 7;
        int kp = (k & ~7) | ((j & 3) << 1) | (j >> 2);   // nibble j -> k-slot
        g_xh[b * IN_F + kp] = __float2half_rn(x[i]);
    }
    if (i < BATCH * OUT_F / 4) {
        float4 b4 = *reinterpret_cast<const float4*>(&bias[(i * 4) % OUT_F]);
        reinterpret_cast<float4*>(out)[i] = b4;
    }
}

// ---------------- main: step-pipelined register-dequant HMMA GEMM ----------------
__global__ __launch_bounds__(THREADS, 4)
void wql_hmma_kernel(const int*   __restrict__ pw,
                     const float* __restrict__ scale,
                     float*       __restrict__ out) {
    extern __shared__ __align__(16) unsigned char dynsm[];
    const uint32_t smb = smem_u32(dynsm);

    const int tid   = threadIdx.x;
    const int wid   = tid >> 5;
    const int lane  = tid & 31;
    const int obase = blockIdx.x * OB;
    const int ks    = blockIdx.y;
    const int kbase = ks * KRANGE;

    const int sh = (lane & 3) * 4;           // dequant shift
    const int r0 = wid * 16 + (lane >> 2);   // A rows r0, r0+8

    const uint32_t aoff = r0 * APITCH_B;
    const uint32_t boff = (((lane >> 4) & 1) * 8 + (lane & 7)) * BPITCH_B
                        + ((lane >> 3) & 1) * 16;

    // staging roles
    const int arow = tid >> 1, ahalf = tid & 1;   // A: 128 rows x 2x32B
    const int brow = tid >> 3, bseg = tid & 7;    // B: 32 rows x 8x32B

    float acc[4][4];
#pragma unroll
    for (int q = 0; q < 4; ++q)
#pragma unroll
        for (int j = 0; j < 4; ++j) acc[q][j] = 0.f;

    // ---- stage chunk 0 ----
    {
        const int* asrc = &pw[(obase + arow) * PWROW + (kbase >> 3) + ahalf * 8];
        uint32_t adst = smb + SA0 + arow * APITCH_B + ahalf * 32;
        cp16(adst, asrc); cp16(adst + 16, asrc + 4);
        const __half* bsrc = &g_xh[brow * IN_F + kbase + bseg * 16];
        uint32_t bdst = smb + SB0 + brow * BPITCH_B + bseg * 32;
        cp16(bdst, bsrc); cp16(bdst + 16, bsrc + 8);
        asm volatile("cp.async.commit_group;" ::: "memory");
    }

    float s_prev0 = 1.f, s_prev1 = 1.f;

#pragma unroll
    for (int c = 0; c < NCH; ++c) {
        const uint32_t ab = smb + (c ? SA1 : SA0);
        const uint32_t bb = smb + (c ? SB1 : SB0);
        asm volatile("cp.async.wait_group 0;" ::: "memory");
        __syncthreads();

        // ---- prefetch chunk c+1 into the other buffers ----
        if (c + 1 < NCH) {
            const int k1 = kbase + (c + 1) * KC;
            const int* asrc = &pw[(obase + arow) * PWROW + (k1 >> 3) + ahalf * 8];
            uint32_t adst = smb + SA1 + arow * APITCH_B + ahalf * 32;
            cp16(adst, asrc); cp16(adst + 16, asrc + 4);
            const __half* bsrc = &g_xh[brow * IN_F + k1 + bseg * 16];
            uint32_t bdst = smb + SB1 + brow * BPITCH_B + bseg * 32;
            cp16(bdst, bsrc); cp16(bdst + 16, bsrc + 8);
            asm volatile("cp.async.commit_group;" ::: "memory");
        }

        // ---- rescale accumulators into this group's raw-int domain ----
        {
            const int gidx = ks * NCH + c;
            float s_cur0 = __ldg(&scale[(obase + r0) * (IN_F / GROUP) + gidx]);
            float s_cur1 = __ldg(&scale[(obase + r0 + 8) * (IN_F / GROUP) + gidx]);
            if (c) {
                float t0 = __fdividef(s_prev0, s_cur0);
                float t1 = __fdividef(s_prev1, s_cur1);
#pragma unroll
                for (int q = 0; q < 4; ++q) {
                    acc[q][0] *= t0; acc[q][1] *= t0;
                    acc[q][2] *= t1; acc[q][3] *= t1;
                }
            }
            s_prev0 = s_cur0; s_prev1 = s_cur1;
        }

        // ---- compute: 8 k16 steps, one-step software pipeline ----
        uint32_t aw[2][4];    // [slot][p0l,p0h,p1l,p1h]
        uint32_t bw[2][8];    // [slot][4 regs nb0 | 4 regs nb1]

        lds64(aw[0][0], aw[0][1], ab + aoff);
        lds64(aw[0][2], aw[0][3], ab + aoff + 8 * APITCH_B);
        ldsm4(bw[0][0], bw[0][1], bw[0][2], bw[0][3], bb + boff);
        ldsm4(bw[0][4], bw[0][5], bw[0][6], bw[0][7], bb + boff + 16 * BPITCH_B);

#pragma unroll
        for (int s = 0; s < 8; ++s) {
            const int cur = s & 1, nxt = cur ^ 1;
            // issue next step's loads first — latency covered by this step's math
            if (s < 7) {
                lds64(aw[nxt][0], aw[nxt][1], ab + aoff + (s + 1) * 8);
                lds64(aw[nxt][2], aw[nxt][3], ab + aoff + 8 * APITCH_B + (s + 1) * 8);
                ldsm4(bw[nxt][0], bw[nxt][1], bw[nxt][2], bw[nxt][3],
                      bb + boff + (s + 1) * 32);
                ldsm4(bw[nxt][4], bw[nxt][5], bw[nxt][6], bw[nxt][7],
                      bb + boff + 16 * BPITCH_B + (s + 1) * 32);
            }
            uint32_t a0 = dqf(aw[cur][0], sh), a2 = dqf(aw[cur][1], sh);
            uint32_t a1 = dqf(aw[cur][2], sh), a3 = dqf(aw[cur][3], sh);

            mma_f16(acc[0], a0, a1, a2, a3, bw[cur][0], bw[cur][1]);
            mma_f16(acc[1], a0, a1, a2, a3, bw[cur][2], bw[cur][3]);
            mma_f16(acc[2], a0, a1, a2, a3, bw[cur][4], bw[cur][5]);
            mma_f16(acc[3], a0, a1, a2, a3, bw[cur][6], bw[cur][7]);
        }
    }

    // ---- epilogue: final scale + atomics ----
    const int orow0 = obase + r0;
#pragma unroll
    for (int q = 0; q < 4; ++q) {
        const int bcol = q * 8 + (lane & 3) * 2;
        atomicAdd(&out[bcol * OUT_F + orow0],           acc[q][0] * s_prev0);
        atomicAdd(&out[(bcol + 1) * OUT_F + orow0],     acc[q][1] * s_prev0);
        atomicAdd(&out[bcol * OUT_F + orow0 + 8],       acc[q][2] * s_prev1);
        atomicAdd(&out[(bcol + 1) * OUT_F + orow0 + 8], acc[q][3] * s_prev1);
    }
}

extern "C" void kernel_launch(void* const* d_in, const int* in_sizes, int n_in,
                              void* d_out, int out_size) {
    const float* x     = (const float*)d_in[0];
    const int*   pw    = (const int*)  d_in[1];
    const float* scale = (const float*)d_in[2];
    const float* bias  = (const float*)d_in[3];
    float* out = (float*)d_out;

    static int smem_set = 0;
    if (!smem_set) {
        cudaFuncSetAttribute(wql_hmma_kernel,
                             cudaFuncAttributeMaxDynamicSharedMemorySize, SMTOT);
        smem_set = 1;
    }

    prep_kernel<<<(BATCH * IN_F + 255) / 256, 256>>>(x, bias, out);
    dim3 grid(OTILES, KSPLIT);
    wql_hmma_kernel<<<grid, THREADS, SMTOT>>>(pw, scale, out);
}

// round 16
// speedup vs baseline: 1.0010x; 1.0010x over previous
#include <cuda_runtime.h>
#include <cuda_fp16.h>
#include <cstdint>

#define OUT_F 11008
#define IN_F  4096
#define BATCH 32
#define GROUP 128

#define OB      128                  // M tile
#define OTILES  (OUT_F / OB)         // 86
#define KSPLIT  16
#define KRANGE  (IN_F / KSPLIT)      // 256
#define KC      128                  // chunk == GROUP (scale-rescale trick)
#define NCH     (KRANGE / KC)        // 2
#define THREADS 256
#define PWROW   (IN_F / 8)           // 512 words per output row

#define APITCH_B 80                  // A packed row pitch (64B data + 16 pad)
#define BPITCH_B 272                 // B row pitch (256B data + 16 pad)

// smem arena (bytes): A 2x10240, B 2x8704
#define SA0 0
#define SA1 10240
#define SB0 20480
#define SB1 29184
#define SMTOT 37888

#define DQ_MASK  0x000f000fu
#define DQ_MAGIC 0x64086408u         // fp16x2 (1032, 1032)

__device__ __half g_xh[BATCH * IN_F];    // x fp16, k-permuted

__device__ __forceinline__ uint32_t smem_u32(const void* p) {
    uint32_t a;
    asm("{ .reg .u64 t; cvta.to.shared.u64 t, %1; cvt.u32.u64 %0, t; }"
        : "=r"(a) : "l"(p));
    return a;
}
__device__ __forceinline__ void ldsm4(uint32_t& r0, uint32_t& r1, uint32_t& r2,
                                      uint32_t& r3, uint32_t addr) {
    asm volatile("ldmatrix.sync.aligned.m8n8.x4.shared.b16 {%0,%1,%2,%3}, [%4];"
                 : "=r"(r0), "=r"(r1), "=r"(r2), "=r"(r3) : "r"(addr));
}
__device__ __forceinline__ void lds128(uint32_t& x, uint32_t& y, uint32_t& z,
                                       uint32_t& w, uint32_t addr) {
    asm volatile("ld.shared.v4.u32 {%0,%1,%2,%3}, [%4];"
                 : "=r"(x), "=r"(y), "=r"(z), "=r"(w) : "r"(addr));
}
__device__ __forceinline__ void mma_f16(float* c,
                                        uint32_t a0, uint32_t a1, uint32_t a2,
                                        uint32_t a3, uint32_t b0, uint32_t b1) {
    asm volatile(
        "mma.sync.aligned.m16n8k16.row.col.f32.f16.f16.f32 "
        "{%0,%1,%2,%3}, {%4,%5,%6,%7}, {%8,%9}, {%0,%1,%2,%3};"
        : "+f"(c[0]), "+f"(c[1]), "+f"(c[2]), "+f"(c[3])
        : "r"(a0), "r"(a1), "r"(a2), "r"(a3), "r"(b0), "r"(b1));
}
__device__ __forceinline__ void cp16(uint32_t saddr, const void* gaddr) {
    asm volatile("cp.async.cg.shared.global [%0], [%1], 16;"
                 :: "r"(saddr), "l"(gaddr) : "memory");
}
// nibbles (c, c+4) of p -> f16x2 of exact signed int4 values
__device__ __forceinline__ uint32_t dqf(uint32_t p, int sh) {
    uint32_t r = ((p >> sh) & DQ_MASK) ^ DQ_MAGIC;
    const uint32_t mg = DQ_MAGIC;
    __half2 h = __hsub2(*reinterpret_cast<__half2*>(&r),
                        *reinterpret_cast<const __half2*>(&mg));
    return *reinterpret_cast<uint32_t*>(&h);
}

// ---------------- prep: x fp16 (k-permuted) + out = bias (float4) ----------------
__global__ void prep_kernel(const float* __restrict__ x,
                            const float* __restrict__ bias,
                            float* __restrict__ out) {
    int i = blockIdx.x * blockDim.x + threadIdx.x;
    if (i < BATCH * IN_F) {
        int b = i >> 12;
        int k = i & (IN_F - 1);
        int j = k & 7;
        int kp = (k & ~7) | ((j & 3) << 1) | (j >> 2);   // nibble j -> k-slot
        g_xh[b * IN_F + kp] = __float2half_rn(x[i]);
    }
    if (i < BATCH * OUT_F / 4) {
        float4 b4 = *reinterpret_cast<const float4*>(&bias[(i * 4) % OUT_F]);
        reinterpret_cast<float4*>(out)[i] = b4;
    }
}

// ---------------- main: upfront-staged, reg-window HMMA GEMM ----------------
__global__ __launch_bounds__(THREADS, 4)
void wql_hmma_kernel(const int*   __restrict__ pw,
                     const float* __restrict__ scale,
                     float*       __restrict__ out) {
    extern __shared__ __align__(16) unsigned char dynsm[];
    const uint32_t smb = smem_u32(dynsm);

    const int tid   = threadIdx.x;
    const int wid   = tid >> 5;
    const int lane  = tid & 31;
    const int obase = blockIdx.x * OB;
    const int ks    = blockIdx.y;
    const int kbase = ks * KRANGE;

    const int sh = (lane & 3) * 4;           // dequant shift
    const int r0 = wid * 16 + (lane >> 2);   // A rows r0, r0+8

    const uint32_t aoff = r0 * APITCH_B;
    const uint32_t boff = (((lane >> 4) & 1) * 8 + (lane & 7)) * BPITCH_B
                        + ((lane >> 3) & 1) * 16;

    // staging roles
    const int arow = tid >> 1, ahalf = tid & 1;   // A: 128 rows x 2x32B
    const int brow = tid >> 3, bseg = tid & 7;    // B: 32 rows x 8x32B

    float acc[4][4];
#pragma unroll
    for (int q = 0; q < 4; ++q)
#pragma unroll
        for (int j = 0; j < 4; ++j) acc[q][j] = 0.f;

    // ---- prologue: stage BOTH chunks (buffers are single-use) ----
#pragma unroll
    for (int c = 0; c < NCH; ++c) {
        const int kc = kbase + c * KC;
        const int* asrc = &pw[(obase + arow) * PWROW + (kc >> 3) + ahalf * 8];
        uint32_t adst = smb + (c ? SA1 : SA0) + arow * APITCH_B + ahalf * 32;
        cp16(adst, asrc); cp16(adst + 16, asrc + 4);
        const __half* bsrc = &g_xh[brow * IN_F + kc + bseg * 16];
        uint32_t bdst = smb + (c ? SB1 : SB0) + brow * BPITCH_B + bseg * 32;
        cp16(bdst, bsrc); cp16(bdst + 16, bsrc + 8);
        asm volatile("cp.async.commit_group;" ::: "memory");
    }

    float s_prev0 = 1.f, s_prev1 = 1.f;

#pragma unroll
    for (int c = 0; c < NCH; ++c) {
        const uint32_t ab = smb + (c ? SA1 : SA0);
        const uint32_t bb = smb + (c ? SB1 : SB0);
        if (c == 0) {
            asm volatile("cp.async.wait_group 1;" ::: "memory");
        } else {
            asm volatile("cp.async.wait_group 0;" ::: "memory");
        }
        __syncthreads();

        // ---- rescale accumulators into this group's raw-int domain ----
        {
            const int gidx = ks * NCH + c;
            float s_cur0 = __ldg(&scale[(obase + r0) * (IN_F / GROUP) + gidx]);
            float s_cur1 = __ldg(&scale[(obase + r0 + 8) * (IN_F / GROUP) + gidx]);
            if (c) {
                float t0 = __fdividef(s_prev0, s_cur0);
                float t1 = __fdividef(s_prev1, s_cur1);
#pragma unroll
                for (int q = 0; q < 4; ++q) {
                    acc[q][0] *= t0; acc[q][1] *= t0;
                    acc[q][2] *= t1; acc[q][3] *= t1;
                }
            }
            s_prev0 = s_cur0; s_prev1 = s_cur1;
        }

        // ---- compute: 2 half-chunks of 4 k16 steps; A words register-resident ----
#pragma unroll
        for (int h = 0; h < 2; ++h) {
            uint32_t ra[8], rb[8];   // row r0 words 8h..8h+7, row r0+8 same
            lds128(ra[0], ra[1], ra[2], ra[3], ab + aoff + h * 32);
            lds128(ra[4], ra[5], ra[6], ra[7], ab + aoff + h * 32 + 16);
            lds128(rb[0], rb[1], rb[2], rb[3], ab + aoff + 8 * APITCH_B + h * 32);
            lds128(rb[4], rb[5], rb[6], rb[7], ab + aoff + 8 * APITCH_B + h * 32 + 16);

#pragma unroll
            for (int s2 = 0; s2 < 4; ++s2) {
                const int s = h * 4 + s2;
                uint32_t a0 = dqf(ra[2 * s2], sh);
                uint32_t a2 = dqf(ra[2 * s2 + 1], sh);
                uint32_t a1 = dqf(rb[2 * s2], sh);
                uint32_t a3 = dqf(rb[2 * s2 + 1], sh);

                uint32_t b0, b1, b2, b3;
                ldsm4(b0, b1, b2, b3, bb + boff + s * 32);
                mma_f16(acc[0], a0, a1, a2, a3, b0, b1);
                mma_f16(acc[1], a0, a1, a2, a3, b2, b3);
                ldsm4(b0, b1, b2, b3, bb + boff + 16 * BPITCH_B + s * 32);
                mma_f16(acc[2], a0, a1, a2, a3, b0, b1);
                mma_f16(acc[3], a0, a1, a2, a3, b2, b3);
            }
        }
    }

    // ---- epilogue: final scale + atomics ----
    const int orow0 = obase + r0;
#pragma unroll
    for (int q = 0; q < 4; ++q) {
        const int bcol = q * 8 + (lane & 3) * 2;
        atomicAdd(&out[bcol * OUT_F + orow0],           acc[q][0] * s_prev0);
        atomicAdd(&out[(bcol + 1) * OUT_F + orow0],     acc[q][1] * s_prev0);
        atomicAdd(&out[bcol * OUT_F + orow0 + 8],       acc[q][2] * s_prev1);
        atomicAdd(&out[(bcol + 1) * OUT_F + orow0 + 8], acc[q][3] * s_prev1);
    }
}

extern "C" void kernel_launch(void* const* d_in, const int* in_sizes, int n_in,
                              void* d_out, int out_size) {
    const float* x     = (const float*)d_in[0];
    const int*   pw    = (const int*)  d_in[1];
    const float* scale = (const float*)d_in[2];
    const float* bias  = (const float*)d_in[3];
    float* out = (float*)d_out;

    static int smem_set = 0;
    if (!smem_set) {
        cudaFuncSetAttribute(wql_hmma_kernel,
                             cudaFuncAttributeMaxDynamicSharedMemorySize, SMTOT);
        smem_set = 1;
    }

    prep_kernel<<<(BATCH * IN_F + 255) / 256, 256>>>(x, bias, out);
    dim3 grid(OTILES, KSPLIT);
    wql_hmma_kernel<<<grid, THREADS, SMTOT>>>(pw, scale, out);
}